// round 12
// baseline (speedup 1.0000x reference)
#include <cuda_runtime.h>
#include <math.h>

#define NS 3
#define SYM 512
#define FD 20
#define NLIN 11
#define NOUT 9
#define HH 2048
#define HIN (NS*SYM*NOUT)   /* 13824 */
#define NO (NS*SYM)         /* 1536 */
#define EPSF 1e-9f

// ---------------- device scratch (no allocations allowed) ----------------
__device__ float g_v[HIN];
__device__ float g_ha[HH];
__device__ float g_hb[HH];
__device__ float g_o[NO];

// DFT twiddles: cos/sin(pi*m/10), m = 0..19 (exact fp32 literals)
__constant__ float c_cs[20] = {
     1.0f,            0.9510565163f,  0.8090169944f,  0.5877852523f,  0.3090169944f,
     0.0f,           -0.3090169944f, -0.5877852523f, -0.8090169944f, -0.9510565163f,
    -1.0f,           -0.9510565163f, -0.8090169944f, -0.5877852523f, -0.3090169944f,
     0.0f,            0.3090169944f,  0.5877852523f,  0.8090169944f,  0.9510565163f
};
__constant__ float c_sn[20] = {
     0.0f,            0.3090169944f,  0.5877852523f,  0.8090169944f,  0.9510565163f,
     1.0f,            0.9510565163f,  0.8090169944f,  0.5877852523f,  0.3090169944f,
     0.0f,           -0.3090169944f, -0.5877852523f, -0.8090169944f, -0.9510565163f,
    -1.0f,           -0.9510565163f, -0.8090169944f, -0.5877852523f, -0.3090169944f
};

// ---------------- front end: inorm -> DFT (table twiddles) -> bilinear -> leaky -> softmax(NS) ----------------
__global__ __launch_bounds__(128) void k_front(const float* __restrict__ wax,
                                               const float* __restrict__ blw,
                                               const float* __restrict__ blb) {
    int s = blockIdx.x;           // 0..511
    int tid = threadIdx.x;
    int warp = tid >> 5, lane = tid & 31;

    __shared__ float sh_xn[NS][FD];
    __shared__ float sh_re[NS][NLIN], sh_im[NS][NLIN];
    __shared__ float sh_z[NS][NOUT];

    if (warp < NS) {
        int b = warp;
        float x = 0.f;
        if (lane < FD) x = wax[(b*SYM + s)*FD + lane];
        float sum = x, sq = x*x;
        #pragma unroll
        for (int o = 16; o > 0; o >>= 1) {
            sum += __shfl_xor_sync(0xffffffffu, sum, o);
            sq  += __shfl_xor_sync(0xffffffffu, sq,  o);
        }
        float m = sum * (1.0f/FD);
        float var = sq * (1.0f/FD) - m*m;
        float r = rsqrtf(var + EPSF);
        if (lane < FD) sh_xn[b][lane] = (x - m) * r;
        __syncwarp();

        if (lane < NLIN) {
            float re = 0.f, im = 0.f;
            int idx = 0;                       // (lane*f) mod 20, tracked incrementally
            #pragma unroll
            for (int f = 0; f < FD; f++) {
                float xv = sh_xn[b][f];
                re += xv * c_cs[idx];
                im -= xv * c_sn[idx];
                idx += lane;
                if (idx >= FD) idx -= FD;
            }
            sh_re[b][lane] = re;
            sh_im[b][lane] = im;
        }
        __syncwarp();

        if (lane < NOUT) {
            int k = lane;
            float z = blb[k];
            #pragma unroll
            for (int i = 0; i < NLIN; i++) {
                float t = 0.f;
                #pragma unroll
                for (int j = 0; j < NLIN; j++)
                    t += blw[(k*NLIN + i)*NLIN + j] * sh_im[b][j];
                z += sh_re[b][i] * t;
            }
            z = (z >= 0.f) ? z : 0.01f*z;   // leaky_relu
            sh_z[b][k] = z;
        }
    }
    __syncthreads();

    if (tid < NOUT) {
        int k = tid;
        float z0 = sh_z[0][k], z1 = sh_z[1][k], z2 = sh_z[2][k];
        float m = fmaxf(z0, fmaxf(z1, z2));
        float e0 = expf(z0-m), e1 = expf(z1-m), e2 = expf(z2-m);
        float inv = 1.f/(e0+e1+e2);
        g_v[s*(NS*NOUT) + 0*NOUT + k] = e0*inv;
        g_v[s*(NS*NOUT) + 1*NOUT + k] = e1*inv;
        g_v[s*(NS*NOUT) + 2*NOUT + k] = e2*inv;
    }
}

__device__ __forceinline__ void pf_l2(const float* p) {
    asm volatile("prefetch.global.L2 [%0];" :: "l"(p));
}

// ---------------- fused LSTM cell (zero state): block computes i,g,o rows of JPB j's ----------------
// PF: bounded L2 prefetch of the NEXT consumer's weights folded into the stream
// (only for the latency-bound H->H cells; cell0 keeps identical codegen with PF=false).
template<int NT, int MINB, int N, int JPB, bool STREAM, bool PF>
__global__ __launch_bounds__(NT, MINB) void k_cell(const float* __restrict__ W,
                                                   const float* __restrict__ x,
                                                   const float* __restrict__ b_ih,
                                                   const float* __restrict__ b_hh,
                                                   float* __restrict__ h,
                                                   const float* __restrict__ pfA,
                                                   unsigned pfAn,
                                                   const float* __restrict__ pfB,
                                                   unsigned pfBn,
                                                   const float* __restrict__ pfC,
                                                   unsigned pfCn) {
    constexpr int N4   = N / 4;
    constexpr int ITER = N4 / NT;       // exact by construction
    constexpr int NR   = 3 * JPB;
    const int j0 = blockIdx.x * JPB;
    const int tid = threadIdx.x;
    const unsigned gid = blockIdx.x * NT + tid;

    const float4* __restrict__ xv = (const float4*)x;
    const float4* Wr[NR];
    #pragma unroll
    for (int q = 0; q < JPB; q++) {
        int j = j0 + q;
        Wr[3*q + 0] = (const float4*)(W + (size_t)(0*HH + j) * N);  // i
        Wr[3*q + 1] = (const float4*)(W + (size_t)(2*HH + j) * N);  // g
        Wr[3*q + 2] = (const float4*)(W + (size_t)(3*HH + j) * N);  // o
    }

    float acc[NR];
    #pragma unroll
    for (int r = 0; r < NR; r++) acc[r] = 0.f;

    #pragma unroll 6
    for (int it = 0; it < ITER; it++) {
        if (PF) {   // one 128B line per thread on selected iterations (bounded, fire-and-forget)
            if (it == 0 && pfA && gid < pfAn) pf_l2(pfA + (size_t)gid * 32);
            if (it == 1 && pfB && gid < pfBn) pf_l2(pfB + (size_t)gid * 32);
            if (it == 2 && pfC && gid < pfCn) pf_l2(pfC + (size_t)gid * 32);
        }
        int t = tid + it * NT;
        float4 v = xv[t];
        #pragma unroll
        for (int r = 0; r < NR; r++) {
            float4 w = STREAM ? __ldcs(&Wr[r][t]) : Wr[r][t];
            acc[r] += w.x*v.x + w.y*v.y + w.z*v.z + w.w*v.w;
        }
    }

    __shared__ float sred[NR][NT/32];
    #pragma unroll
    for (int r = 0; r < NR; r++) {
        float a = acc[r];
        #pragma unroll
        for (int o = 16; o > 0; o >>= 1) a += __shfl_xor_sync(0xffffffffu, a, o);
        if ((tid & 31) == 0) sred[r][tid >> 5] = a;
    }
    __syncthreads();

    if (tid < JPB) {
        int q = tid, j = j0 + q;
        float gi = 0.f, gg = 0.f, go = 0.f;
        #pragma unroll
        for (int w = 0; w < NT/32; w++) {
            gi += sred[3*q + 0][w];
            gg += sred[3*q + 1][w];
            go += sred[3*q + 2][w];
        }
        gi += b_ih[j]        + b_hh[j];
        gg += b_ih[2*HH + j] + b_hh[2*HH + j];
        go += b_ih[3*HH + j] + b_hh[3*HH + j];
        float si = 1.f / (1.f + __expf(-gi));
        float so = 1.f / (1.f + __expf(-go));
        float c  = si * tanhf(gg);
        h[j] = so * tanhf(c);
    }
}

// ---------------- warp-per-row linear head (lin_w L2-warm from cell2's prefetch) ----------------
template<int N, int WPB, int UNR>
__global__ __launch_bounds__(WPB*32) void k_linw(const float* __restrict__ W,
                                                 const float* __restrict__ x,
                                                 const float* __restrict__ b,
                                                 float* __restrict__ out) {
    constexpr int R = N / 128;
    const int warp = threadIdx.x >> 5, lane = threadIdx.x & 31;
    const int row = blockIdx.x * WPB + warp;

    const float4* __restrict__ xv = (const float4*)x;
    const float4* __restrict__ wr = (const float4*)(W + (size_t)row * N);

    float acc = 0.f;
    #pragma unroll UNR
    for (int k = 0; k < R; k++) {
        int t = lane + 32*k;
        float4 v = xv[t];
        float4 w = wr[t];
        acc += w.x*v.x + w.y*v.y + w.z*v.z + w.w*v.w;
    }
    #pragma unroll
    for (int o = 16; o > 0; o >>= 1) acc += __shfl_xor_sync(0xffffffffu, acc, o);
    if (lane == 0) out[row] = acc + b[row];
}

// ---------------- final: inorm(512) -> leaky -> softmax(512), 3 blocks ----------------
__device__ __forceinline__ float blk_sum512(float v, volatile float* sh) {
    int t = threadIdx.x;
    #pragma unroll
    for (int o = 16; o > 0; o >>= 1) v += __shfl_xor_sync(0xffffffffu, v, o);
    if ((t & 31) == 0) sh[t >> 5] = v;
    __syncthreads();
    if (t == 0) {
        float a = 0.f;
        #pragma unroll
        for (int w = 0; w < 16; w++) a += sh[w];
        sh[16] = a;
    }
    __syncthreads();
    float r = sh[16];
    __syncthreads();
    return r;
}

__device__ __forceinline__ float blk_max512(float v, volatile float* sh) {
    int t = threadIdx.x;
    #pragma unroll
    for (int o = 16; o > 0; o >>= 1) v = fmaxf(v, __shfl_xor_sync(0xffffffffu, v, o));
    if ((t & 31) == 0) sh[t >> 5] = v;
    __syncthreads();
    if (t == 0) {
        float a = -3.4e38f;
        #pragma unroll
        for (int w = 0; w < 16; w++) a = fmaxf(a, sh[w]);
        sh[16] = a;
    }
    __syncthreads();
    float r = sh[16];
    __syncthreads();
    return r;
}

__global__ __launch_bounds__(512) void k_final(float* __restrict__ out) {
    __shared__ float sh[17];
    int b = blockIdx.x;   // 0..2
    int t = threadIdx.x;  // 0..511
    float v = g_o[b*SYM + t];
    float sum = blk_sum512(v, sh);
    float sq  = blk_sum512(v*v, sh);
    float m = sum * (1.0f/SYM);
    float var = sq * (1.0f/SYM) - m*m;
    float xn = (v - m) * rsqrtf(var + EPSF);
    xn = (xn >= 0.f) ? xn : 0.01f*xn;
    float mx = blk_max512(xn, sh);
    float e = expf(xn - mx);
    float se = blk_sum512(e, sh);
    out[b*SYM + t] = e / se;
}

// ---------------- launch ----------------
extern "C" void kernel_launch(void* const* d_in, const int* in_sizes, int n_in,
                              void* d_out, int out_size) {
    const float* wax   = (const float*)d_in[0];
    const float* blw   = (const float*)d_in[1];
    const float* blb   = (const float*)d_in[2];
    const float* w_ih0 = (const float*)d_in[3];
    // d_in[4] = w_hh0 (unused: h0 = 0)
    const float* b_ih0 = (const float*)d_in[5];
    const float* b_hh0 = (const float*)d_in[6];
    const float* w_ih1 = (const float*)d_in[7];
    const float* b_ih1 = (const float*)d_in[9];
    const float* b_hh1 = (const float*)d_in[10];
    const float* w_ih2 = (const float*)d_in[11];
    const float* b_ih2 = (const float*)d_in[13];
    const float* b_hh2 = (const float*)d_in[14];
    const float* lin_w = (const float*)d_in[15];
    const float* lin_b = (const float*)d_in[16];
    float* out = (float*)d_out;

    static float *p_v = nullptr, *p_ha = nullptr, *p_hb = nullptr, *p_o = nullptr;
    if (!p_v) {
        cudaGetSymbolAddress((void**)&p_v,  g_v);
        cudaGetSymbolAddress((void**)&p_ha, g_ha);
        cudaGetSymbolAddress((void**)&p_hb, g_hb);
        cudaGetSymbolAddress((void**)&p_o,  g_o);
    }

    const unsigned GLINES = (unsigned)((size_t)HH*HH*4/128);   // 131072 lines per gate region
    const unsigned LLINES = (unsigned)((size_t)NO*HH*4/128);   // 98304 lines in lin_w

    k_front<<<SYM, 128>>>(wax, blw, blb);

    // cell 0: proven config (NT=192, MINB=8, ITER=18, grid 2048, ~DRAM roofline). No prefetch.
    k_cell<192, 8, HIN, 1, true, false><<<HH, 192>>>(w_ih0, p_v, b_ih0, b_hh0, p_ha,
                                                     nullptr, 0u, nullptr, 0u, nullptr, 0u);

    // cell 1: proven config + prefetch ALL of w_ih2 (i, g, o regions = 50 MB)
    // into cell1's idle DRAM headroom so cell2's whole stream is L2-hot.
    k_cell<128, 8, HH, 2, true, true><<<HH/2, 128>>>(w_ih1, p_ha, b_ih1, b_hh1, p_hb,
                                                     w_ih2 + (size_t)0*HH*HH, GLINES,
                                                     w_ih2 + (size_t)2*HH*HH, GLINES,
                                                     w_ih2 + (size_t)3*HH*HH, GLINES);

    // cell 2: proven config + prefetch of lin_w (12.6 MB).
    k_cell<128, 8, HH, 2, true, true><<<HH/2, 128>>>(w_ih2, p_hb, b_ih2, b_hh2, p_ha,
                                                     lin_w, LLINES, nullptr, 0u, nullptr, 0u);

    // linear head: warp-per-row (default-cached; L2-hot).
    k_linw<HH, 4, 8><<<NO/4, 128>>>(lin_w, p_ha, lin_b, p_o);

    k_final<<<NS, 512>>>(out);
}

// round 13
// speedup vs baseline: 1.0884x; 1.0884x over previous
#include <cuda_runtime.h>
#include <math.h>

#define NS 3
#define SYM 512
#define FD 20
#define NLIN 11
#define NOUT 9
#define HH 2048
#define HIN (NS*SYM*NOUT)   /* 13824 */
#define NO (NS*SYM)         /* 1536 */
#define EPSF 1e-9f

// ---------------- device scratch (no allocations allowed) ----------------
__device__ float g_v[HIN];
__device__ float g_ha[HH];
__device__ float g_hb[HH];
__device__ float g_o[NO];

// DFT twiddles: cos/sin(pi*m/10), m = 0..19 (exact fp32 literals)
__constant__ float c_cs[20] = {
     1.0f,            0.9510565163f,  0.8090169944f,  0.5877852523f,  0.3090169944f,
     0.0f,           -0.3090169944f, -0.5877852523f, -0.8090169944f, -0.9510565163f,
    -1.0f,           -0.9510565163f, -0.8090169944f, -0.5877852523f, -0.3090169944f,
     0.0f,            0.3090169944f,  0.5877852523f,  0.8090169944f,  0.9510565163f
};
__constant__ float c_sn[20] = {
     0.0f,            0.3090169944f,  0.5877852523f,  0.8090169944f,  0.9510565163f,
     1.0f,            0.9510565163f,  0.8090169944f,  0.5877852523f,  0.3090169944f,
     0.0f,           -0.3090169944f, -0.5877852523f, -0.8090169944f, -0.9510565163f,
    -1.0f,           -0.9510565163f, -0.8090169944f, -0.5877852523f, -0.3090169944f
};

// ---------------- front end: inorm -> DFT (table twiddles) -> bilinear -> leaky -> softmax(NS) ----------------
__global__ __launch_bounds__(128) void k_front(const float* __restrict__ wax,
                                               const float* __restrict__ blw,
                                               const float* __restrict__ blb) {
    int s = blockIdx.x;           // 0..511
    int tid = threadIdx.x;
    int warp = tid >> 5, lane = tid & 31;

    __shared__ float sh_xn[NS][FD];
    __shared__ float sh_re[NS][NLIN], sh_im[NS][NLIN];
    __shared__ float sh_z[NS][NOUT];

    if (warp < NS) {
        int b = warp;
        float x = 0.f;
        if (lane < FD) x = wax[(b*SYM + s)*FD + lane];
        float sum = x, sq = x*x;
        #pragma unroll
        for (int o = 16; o > 0; o >>= 1) {
            sum += __shfl_xor_sync(0xffffffffu, sum, o);
            sq  += __shfl_xor_sync(0xffffffffu, sq,  o);
        }
        float m = sum * (1.0f/FD);
        float var = sq * (1.0f/FD) - m*m;
        float r = rsqrtf(var + EPSF);
        if (lane < FD) sh_xn[b][lane] = (x - m) * r;
        __syncwarp();

        if (lane < NLIN) {
            float re = 0.f, im = 0.f;
            int idx = 0;                       // (lane*f) mod 20, tracked incrementally
            #pragma unroll
            for (int f = 0; f < FD; f++) {
                float xv = sh_xn[b][f];
                re += xv * c_cs[idx];
                im -= xv * c_sn[idx];
                idx += lane;
                if (idx >= FD) idx -= FD;
            }
            sh_re[b][lane] = re;
            sh_im[b][lane] = im;
        }
        __syncwarp();

        if (lane < NOUT) {
            int k = lane;
            float z = blb[k];
            #pragma unroll
            for (int i = 0; i < NLIN; i++) {
                float t = 0.f;
                #pragma unroll
                for (int j = 0; j < NLIN; j++)
                    t += blw[(k*NLIN + i)*NLIN + j] * sh_im[b][j];
                z += sh_re[b][i] * t;
            }
            z = (z >= 0.f) ? z : 0.01f*z;   // leaky_relu
            sh_z[b][k] = z;
        }
    }
    __syncthreads();

    if (tid < NOUT) {
        int k = tid;
        float z0 = sh_z[0][k], z1 = sh_z[1][k], z2 = sh_z[2][k];
        float m = fmaxf(z0, fmaxf(z1, z2));
        float e0 = expf(z0-m), e1 = expf(z1-m), e2 = expf(z2-m);
        float inv = 1.f/(e0+e1+e2);
        g_v[s*(NS*NOUT) + 0*NOUT + k] = e0*inv;
        g_v[s*(NS*NOUT) + 1*NOUT + k] = e1*inv;
        g_v[s*(NS*NOUT) + 2*NOUT + k] = e2*inv;
    }
}

__device__ __forceinline__ void pf_l2(const float* p) {
    asm volatile("prefetch.global.L2 [%0];" :: "l"(p));
}

// ---------------- fused LSTM cell (zero state): block computes i,g,o rows of JPB j's ----------------
// PDL: launched with programmatic stream serialization. Weight pointer setup and a
// self-prefetch of the first iteration's weight lines run BEFORE
// cudaGridDependencySynchronize() (they don't depend on the predecessor); the x-consuming
// main loop runs after. PF adds bounded L2 prefetch of the NEXT consumer's weights.
template<int NT, int MINB, int N, int JPB, bool STREAM, bool PF>
__global__ __launch_bounds__(NT, MINB) void k_cell(const float* __restrict__ W,
                                                   const float* __restrict__ x,
                                                   const float* __restrict__ b_ih,
                                                   const float* __restrict__ b_hh,
                                                   float* __restrict__ h,
                                                   const float* __restrict__ pfA,
                                                   unsigned pfAn,
                                                   const float* __restrict__ pfB,
                                                   unsigned pfBn) {
    constexpr int N4   = N / 4;
    constexpr int ITER = N4 / NT;       // exact by construction
    constexpr int NR   = 3 * JPB;
    const int j0 = blockIdx.x * JPB;
    const int tid = threadIdx.x;
    const unsigned gid = blockIdx.x * NT + tid;

    const float4* __restrict__ xv = (const float4*)x;
    const float4* Wr[NR];
    #pragma unroll
    for (int q = 0; q < JPB; q++) {
        int j = j0 + q;
        Wr[3*q + 0] = (const float4*)(W + (size_t)(0*HH + j) * N);  // i
        Wr[3*q + 1] = (const float4*)(W + (size_t)(2*HH + j) * N);  // g
        Wr[3*q + 2] = (const float4*)(W + (size_t)(3*HH + j) * N);  // o
    }

    // predecessor-independent prologue: warm own first-iteration weight lines
    #pragma unroll
    for (int r = 0; r < NR; r++) pf_l2((const float*)(Wr[r] + tid));

    cudaGridDependencySynchronize();    // wait for predecessor's writes (x)

    float acc[NR];
    #pragma unroll
    for (int r = 0; r < NR; r++) acc[r] = 0.f;

    #pragma unroll 6
    for (int it = 0; it < ITER; it++) {
        if (PF) {   // one 128B line per thread on selected iterations (bounded, fire-and-forget)
            if (it == 0 && pfA && gid < pfAn) pf_l2(pfA + (size_t)gid * 32);
            if (it == 1 && pfB && gid < pfBn) pf_l2(pfB + (size_t)gid * 32);
        }
        int t = tid + it * NT;
        float4 v = xv[t];
        #pragma unroll
        for (int r = 0; r < NR; r++) {
            float4 w = STREAM ? __ldcs(&Wr[r][t]) : Wr[r][t];
            acc[r] += w.x*v.x + w.y*v.y + w.z*v.z + w.w*v.w;
        }
    }

    __shared__ float sred[NR][NT/32];
    #pragma unroll
    for (int r = 0; r < NR; r++) {
        float a = acc[r];
        #pragma unroll
        for (int o = 16; o > 0; o >>= 1) a += __shfl_xor_sync(0xffffffffu, a, o);
        if ((tid & 31) == 0) sred[r][tid >> 5] = a;
    }
    __syncthreads();

    if (tid < JPB) {
        int q = tid, j = j0 + q;
        float gi = 0.f, gg = 0.f, go = 0.f;
        #pragma unroll
        for (int w = 0; w < NT/32; w++) {
            gi += sred[3*q + 0][w];
            gg += sred[3*q + 1][w];
            go += sred[3*q + 2][w];
        }
        gi += b_ih[j]        + b_hh[j];
        gg += b_ih[2*HH + j] + b_hh[2*HH + j];
        go += b_ih[3*HH + j] + b_hh[3*HH + j];
        float si = 1.f / (1.f + __expf(-gi));
        float so = 1.f / (1.f + __expf(-go));
        float c  = si * tanhf(gg);
        h[j] = so * tanhf(c);
    }
}

// ---------------- warp-per-row linear head (PDL; lin_w L2-warm from cell2's prefetch) ----------------
template<int N, int WPB, int UNR>
__global__ __launch_bounds__(WPB*32) void k_linw(const float* __restrict__ W,
                                                 const float* __restrict__ x,
                                                 const float* __restrict__ b,
                                                 float* __restrict__ out) {
    constexpr int R = N / 128;
    const int warp = threadIdx.x >> 5, lane = threadIdx.x & 31;
    const int row = blockIdx.x * WPB + warp;

    const float4* __restrict__ xv = (const float4*)x;
    const float4* __restrict__ wr = (const float4*)(W + (size_t)row * N);

    pf_l2((const float*)(wr + lane));        // predecessor-independent warm
    cudaGridDependencySynchronize();

    float acc = 0.f;
    #pragma unroll UNR
    for (int k = 0; k < R; k++) {
        int t = lane + 32*k;
        float4 v = xv[t];
        float4 w = wr[t];
        acc += w.x*v.x + w.y*v.y + w.z*v.z + w.w*v.w;
    }
    #pragma unroll
    for (int o = 16; o > 0; o >>= 1) acc += __shfl_xor_sync(0xffffffffu, acc, o);
    if (lane == 0) out[row] = acc + b[row];
}

// ---------------- final: inorm(512) -> leaky -> softmax(512), 3 blocks (PDL) ----------------
__device__ __forceinline__ float blk_sum512(float v, volatile float* sh) {
    int t = threadIdx.x;
    #pragma unroll
    for (int o = 16; o > 0; o >>= 1) v += __shfl_xor_sync(0xffffffffu, v, o);
    if ((t & 31) == 0) sh[t >> 5] = v;
    __syncthreads();
    if (t == 0) {
        float a = 0.f;
        #pragma unroll
        for (int w = 0; w < 16; w++) a += sh[w];
        sh[16] = a;
    }
    __syncthreads();
    float r = sh[16];
    __syncthreads();
    return r;
}

__device__ __forceinline__ float blk_max512(float v, volatile float* sh) {
    int t = threadIdx.x;
    #pragma unroll
    for (int o = 16; o > 0; o >>= 1) v = fmaxf(v, __shfl_xor_sync(0xffffffffu, v, o));
    if ((t & 31) == 0) sh[t >> 5] = v;
    __syncthreads();
    if (t == 0) {
        float a = -3.4e38f;
        #pragma unroll
        for (int w = 0; w < 16; w++) a = fmaxf(a, sh[w]);
        sh[16] = a;
    }
    __syncthreads();
    float r = sh[16];
    __syncthreads();
    return r;
}

__global__ __launch_bounds__(512) void k_final(float* __restrict__ out) {
    __shared__ float sh[17];
    cudaGridDependencySynchronize();
    int b = blockIdx.x;   // 0..2
    int t = threadIdx.x;  // 0..511
    float v = g_o[b*SYM + t];
    float sum = blk_sum512(v, sh);
    float sq  = blk_sum512(v*v, sh);
    float m = sum * (1.0f/SYM);
    float var = sq * (1.0f/SYM) - m*m;
    float xn = (v - m) * rsqrtf(var + EPSF);
    xn = (xn >= 0.f) ? xn : 0.01f*xn;
    float mx = blk_max512(xn, sh);
    float e = expf(xn - mx);
    float se = blk_sum512(e, sh);
    out[b*SYM + t] = e / se;
}

// ---------------- PDL launch helper ----------------
template<typename F, typename... Args>
static void pdl_launch(dim3 grid, dim3 block, F* fn, Args... args) {
    cudaLaunchConfig_t cfg = {};
    cfg.gridDim = grid;
    cfg.blockDim = block;
    cfg.dynamicSmemBytes = 0;
    cfg.stream = 0;                        // legacy default stream (captured)
    cudaLaunchAttribute at[1];
    at[0].id = cudaLaunchAttributeProgrammaticStreamSerialization;
    at[0].val.programmaticStreamSerializationAllowed = 1;
    cfg.attrs = at;
    cfg.numAttrs = 1;
    cudaLaunchKernelEx(&cfg, fn, args...);
}

// ---------------- launch ----------------
extern "C" void kernel_launch(void* const* d_in, const int* in_sizes, int n_in,
                              void* d_out, int out_size) {
    const float* wax   = (const float*)d_in[0];
    const float* blw   = (const float*)d_in[1];
    const float* blb   = (const float*)d_in[2];
    const float* w_ih0 = (const float*)d_in[3];
    // d_in[4] = w_hh0 (unused: h0 = 0)
    const float* b_ih0 = (const float*)d_in[5];
    const float* b_hh0 = (const float*)d_in[6];
    const float* w_ih1 = (const float*)d_in[7];
    const float* b_ih1 = (const float*)d_in[9];
    const float* b_hh1 = (const float*)d_in[10];
    const float* w_ih2 = (const float*)d_in[11];
    const float* b_ih2 = (const float*)d_in[13];
    const float* b_hh2 = (const float*)d_in[14];
    const float* lin_w = (const float*)d_in[15];
    const float* lin_b = (const float*)d_in[16];
    float* out = (float*)d_out;

    static float *p_v = nullptr, *p_ha = nullptr, *p_hb = nullptr, *p_o = nullptr;
    if (!p_v) {
        cudaGetSymbolAddress((void**)&p_v,  g_v);
        cudaGetSymbolAddress((void**)&p_ha, g_ha);
        cudaGetSymbolAddress((void**)&p_hb, g_hb);
        cudaGetSymbolAddress((void**)&p_o,  g_o);
    }

    const unsigned GLINES = (unsigned)((size_t)HH*HH*4/128);   // 131072 lines per gate region

    k_front<<<SYM, 128>>>(wax, blw, blb);

    // cell 0: proven config (NT=192, MINB=8, ITER=18, grid 2048, ~DRAM roofline). PDL off k_front.
    pdl_launch(dim3(HH), dim3(192),
               &k_cell<192, 8, HIN, 1, true, false>,
               w_ih0, (const float*)p_v, b_ih0, b_hh0, (float*)p_ha,
               (const float*)nullptr, 0u, (const float*)nullptr, 0u);

    // cell 1: proven config + 2-pass prefetch of w_ih2 (i and g regions; R11 best). PDL off cell0.
    pdl_launch(dim3(HH/2), dim3(128),
               &k_cell<128, 8, HH, 2, true, true>,
               w_ih1, (const float*)p_ha, b_ih1, b_hh1, (float*)p_hb,
               (const float*)(w_ih2 + (size_t)0*HH*HH), GLINES,
               (const float*)(w_ih2 + (size_t)2*HH*HH), GLINES);

    // cell 2: proven config + prefetch of lin_w. PDL off cell1.
    pdl_launch(dim3(HH/2), dim3(128),
               &k_cell<128, 8, HH, 2, true, true>,
               w_ih2, (const float*)p_hb, b_ih2, b_hh2, (float*)p_ha,
               (const float*)lin_w, (unsigned)((size_t)NO*HH*4/128),
               (const float*)nullptr, 0u);

    // linear head: warp-per-row (L2-hot). PDL off cell2.
    pdl_launch(dim3(NO/4), dim3(128),
               &k_linw<HH, 4, 8>,
               lin_w, (const float*)p_ha, lin_b, (float*)p_o);

    // finalize. PDL off lin.
    pdl_launch(dim3(NS), dim3(512), &k_final, out);
}

// round 14
// speedup vs baseline: 1.0925x; 1.0038x over previous
#include <cuda_runtime.h>
#include <math.h>

#define NS 3
#define SYM 512
#define FD 20
#define NLIN 11
#define NOUT 9
#define HH 2048
#define HIN (NS*SYM*NOUT)   /* 13824 */
#define NO (NS*SYM)         /* 1536 */
#define EPSF 1e-9f

// ---------------- device scratch (no allocations allowed) ----------------
__device__ float g_v[HIN];
__device__ float g_ha[HH];
__device__ float g_hb[HH];
__device__ float g_o[NO];

// DFT twiddles: cos/sin(pi*m/10), m = 0..19 (exact fp32 literals)
__constant__ float c_cs[20] = {
     1.0f,            0.9510565163f,  0.8090169944f,  0.5877852523f,  0.3090169944f,
     0.0f,           -0.3090169944f, -0.5877852523f, -0.8090169944f, -0.9510565163f,
    -1.0f,           -0.9510565163f, -0.8090169944f, -0.5877852523f, -0.3090169944f,
     0.0f,            0.3090169944f,  0.5877852523f,  0.8090169944f,  0.9510565163f
};
__constant__ float c_sn[20] = {
     0.0f,            0.3090169944f,  0.5877852523f,  0.8090169944f,  0.9510565163f,
     1.0f,            0.9510565163f,  0.8090169944f,  0.5877852523f,  0.3090169944f,
     0.0f,           -0.3090169944f, -0.5877852523f, -0.8090169944f, -0.9510565163f,
    -1.0f,           -0.9510565163f, -0.8090169944f, -0.5877852523f, -0.3090169944f
};

// ---------------- front end: inorm -> DFT (table twiddles) -> bilinear -> leaky -> softmax(NS) ----------------
__global__ __launch_bounds__(128) void k_front(const float* __restrict__ wax,
                                               const float* __restrict__ blw,
                                               const float* __restrict__ blb) {
    int s = blockIdx.x;           // 0..511
    int tid = threadIdx.x;
    int warp = tid >> 5, lane = tid & 31;

    __shared__ float sh_xn[NS][FD];
    __shared__ float sh_re[NS][NLIN], sh_im[NS][NLIN];
    __shared__ float sh_z[NS][NOUT];

    if (warp < NS) {
        int b = warp;
        float x = 0.f;
        if (lane < FD) x = wax[(b*SYM + s)*FD + lane];
        float sum = x, sq = x*x;
        #pragma unroll
        for (int o = 16; o > 0; o >>= 1) {
            sum += __shfl_xor_sync(0xffffffffu, sum, o);
            sq  += __shfl_xor_sync(0xffffffffu, sq,  o);
        }
        float m = sum * (1.0f/FD);
        float var = sq * (1.0f/FD) - m*m;
        float r = rsqrtf(var + EPSF);
        if (lane < FD) sh_xn[b][lane] = (x - m) * r;
        __syncwarp();

        if (lane < NLIN) {
            float re = 0.f, im = 0.f;
            int idx = 0;                       // (lane*f) mod 20, tracked incrementally
            #pragma unroll
            for (int f = 0; f < FD; f++) {
                float xv = sh_xn[b][f];
                re += xv * c_cs[idx];
                im -= xv * c_sn[idx];
                idx += lane;
                if (idx >= FD) idx -= FD;
            }
            sh_re[b][lane] = re;
            sh_im[b][lane] = im;
        }
        __syncwarp();

        if (lane < NOUT) {
            int k = lane;
            float z = blb[k];
            #pragma unroll
            for (int i = 0; i < NLIN; i++) {
                float t = 0.f;
                #pragma unroll
                for (int j = 0; j < NLIN; j++)
                    t += blw[(k*NLIN + i)*NLIN + j] * sh_im[b][j];
                z += sh_re[b][i] * t;
            }
            z = (z >= 0.f) ? z : 0.01f*z;   // leaky_relu
            sh_z[b][k] = z;
        }
    }
    __syncthreads();

    if (tid < NOUT) {
        int k = tid;
        float z0 = sh_z[0][k], z1 = sh_z[1][k], z2 = sh_z[2][k];
        float m = fmaxf(z0, fmaxf(z1, z2));
        float e0 = expf(z0-m), e1 = expf(z1-m), e2 = expf(z2-m);
        float inv = 1.f/(e0+e1+e2);
        g_v[s*(NS*NOUT) + 0*NOUT + k] = e0*inv;
        g_v[s*(NS*NOUT) + 1*NOUT + k] = e1*inv;
        g_v[s*(NS*NOUT) + 2*NOUT + k] = e2*inv;
    }
}

__device__ __forceinline__ void pf_l2(const float* p) {
    asm volatile("prefetch.global.L2 [%0];" :: "l"(p));
}

// ---------------- fused LSTM cell (zero state): block computes i,g,o rows of JPB j's ----------------
// PDL: weight pointer setup + self-prefetch run BEFORE cudaGridDependencySynchronize()
// (predecessor-independent), landing in the predecessor's drain-wave DRAM headroom.
// PROITER: how many iterations of own weight lines to prefetch pre-sync
//          (H->H cells: ALL of them; cell0: just the first).
// PF: bounded in-loop L2 prefetch of the NEXT consumer's weights.
template<int NT, int MINB, int N, int JPB, bool STREAM, bool PF, int PROITER>
__global__ __launch_bounds__(NT, MINB) void k_cell(const float* __restrict__ W,
                                                   const float* __restrict__ x,
                                                   const float* __restrict__ b_ih,
                                                   const float* __restrict__ b_hh,
                                                   float* __restrict__ h,
                                                   const float* __restrict__ pfA,
                                                   unsigned pfAn,
                                                   const float* __restrict__ pfB,
                                                   unsigned pfBn) {
    constexpr int N4   = N / 4;
    constexpr int ITER = N4 / NT;       // exact by construction
    constexpr int NR   = 3 * JPB;
    const int j0 = blockIdx.x * JPB;
    const int tid = threadIdx.x;
    const unsigned gid = blockIdx.x * NT + tid;

    const float4* __restrict__ xv = (const float4*)x;
    const float4* Wr[NR];
    #pragma unroll
    for (int q = 0; q < JPB; q++) {
        int j = j0 + q;
        Wr[3*q + 0] = (const float4*)(W + (size_t)(0*HH + j) * N);  // i
        Wr[3*q + 1] = (const float4*)(W + (size_t)(2*HH + j) * N);  // g
        Wr[3*q + 2] = (const float4*)(W + (size_t)(3*HH + j) * N);  // o
    }

    // predecessor-independent prologue: warm own weight lines into L2
    #pragma unroll
    for (int it = 0; it < PROITER; it++) {
        #pragma unroll
        for (int r = 0; r < NR; r++) pf_l2((const float*)(Wr[r] + tid + it*NT));
    }

    cudaGridDependencySynchronize();    // wait for predecessor's writes (x)

    float acc[NR];
    #pragma unroll
    for (int r = 0; r < NR; r++) acc[r] = 0.f;

    #pragma unroll 6
    for (int it = 0; it < ITER; it++) {
        if (PF) {   // one 128B line per thread on selected iterations (bounded, fire-and-forget)
            if (it == 0 && pfA && gid < pfAn) pf_l2(pfA + (size_t)gid * 32);
            if (it == 1 && pfB && gid < pfBn) pf_l2(pfB + (size_t)gid * 32);
        }
        int t = tid + it * NT;
        float4 v = xv[t];
        #pragma unroll
        for (int r = 0; r < NR; r++) {
            float4 w = STREAM ? __ldcs(&Wr[r][t]) : Wr[r][t];
            acc[r] += w.x*v.x + w.y*v.y + w.z*v.z + w.w*v.w;
        }
    }

    __shared__ float sred[NR][NT/32];
    #pragma unroll
    for (int r = 0; r < NR; r++) {
        float a = acc[r];
        #pragma unroll
        for (int o = 16; o > 0; o >>= 1) a += __shfl_xor_sync(0xffffffffu, a, o);
        if ((tid & 31) == 0) sred[r][tid >> 5] = a;
    }
    __syncthreads();

    if (tid < JPB) {
        int q = tid, j = j0 + q;
        float gi = 0.f, gg = 0.f, go = 0.f;
        #pragma unroll
        for (int w = 0; w < NT/32; w++) {
            gi += sred[3*q + 0][w];
            gg += sred[3*q + 1][w];
            go += sred[3*q + 2][w];
        }
        gi += b_ih[j]        + b_hh[j];
        gg += b_ih[2*HH + j] + b_hh[2*HH + j];
        go += b_ih[3*HH + j] + b_hh[3*HH + j];
        float si = 1.f / (1.f + __expf(-gi));
        float so = 1.f / (1.f + __expf(-go));
        float c  = si * tanhf(gg);
        h[j] = so * tanhf(c);
    }
}

// ---------------- warp-per-row linear head (PDL; full own-stream prologue prefetch) ----------------
template<int N, int WPB, int UNR>
__global__ __launch_bounds__(WPB*32) void k_linw(const float* __restrict__ W,
                                                 const float* __restrict__ x,
                                                 const float* __restrict__ b,
                                                 float* __restrict__ out) {
    constexpr int R = N / 128;
    const int warp = threadIdx.x >> 5, lane = threadIdx.x & 31;
    const int row = blockIdx.x * WPB + warp;

    const float4* __restrict__ xv = (const float4*)x;
    const float4* __restrict__ wr = (const float4*)(W + (size_t)row * N);

    #pragma unroll
    for (int k = 0; k < R; k++) pf_l2((const float*)(wr + lane + 32*k));  // pre-sync warm
    cudaGridDependencySynchronize();

    float acc = 0.f;
    #pragma unroll UNR
    for (int k = 0; k < R; k++) {
        int t = lane + 32*k;
        float4 v = xv[t];
        float4 w = wr[t];
        acc += w.x*v.x + w.y*v.y + w.z*v.z + w.w*v.w;
    }
    #pragma unroll
    for (int o = 16; o > 0; o >>= 1) acc += __shfl_xor_sync(0xffffffffu, acc, o);
    if (lane == 0) out[row] = acc + b[row];
}

// ---------------- final: inorm(512) -> leaky -> softmax(512), 3 blocks (PDL) ----------------
__device__ __forceinline__ float blk_sum512(float v, volatile float* sh) {
    int t = threadIdx.x;
    #pragma unroll
    for (int o = 16; o > 0; o >>= 1) v += __shfl_xor_sync(0xffffffffu, v, o);
    if ((t & 31) == 0) sh[t >> 5] = v;
    __syncthreads();
    if (t == 0) {
        float a = 0.f;
        #pragma unroll
        for (int w = 0; w < 16; w++) a += sh[w];
        sh[16] = a;
    }
    __syncthreads();
    float r = sh[16];
    __syncthreads();
    return r;
}

__device__ __forceinline__ float blk_max512(float v, volatile float* sh) {
    int t = threadIdx.x;
    #pragma unroll
    for (int o = 16; o > 0; o >>= 1) v = fmaxf(v, __shfl_xor_sync(0xffffffffu, v, o));
    if ((t & 31) == 0) sh[t >> 5] = v;
    __syncthreads();
    if (t == 0) {
        float a = -3.4e38f;
        #pragma unroll
        for (int w = 0; w < 16; w++) a = fmaxf(a, sh[w]);
        sh[16] = a;
    }
    __syncthreads();
    float r = sh[16];
    __syncthreads();
    return r;
}

__global__ __launch_bounds__(512) void k_final(float* __restrict__ out) {
    __shared__ float sh[17];
    cudaGridDependencySynchronize();
    int b = blockIdx.x;   // 0..2
    int t = threadIdx.x;  // 0..511
    float v = g_o[b*SYM + t];
    float sum = blk_sum512(v, sh);
    float sq  = blk_sum512(v*v, sh);
    float m = sum * (1.0f/SYM);
    float var = sq * (1.0f/SYM) - m*m;
    float xn = (v - m) * rsqrtf(var + EPSF);
    xn = (xn >= 0.f) ? xn : 0.01f*xn;
    float mx = blk_max512(xn, sh);
    float e = expf(xn - mx);
    float se = blk_sum512(e, sh);
    out[b*SYM + t] = e / se;
}

// ---------------- PDL launch helper ----------------
template<typename F, typename... Args>
static void pdl_launch(dim3 grid, dim3 block, F* fn, Args... args) {
    cudaLaunchConfig_t cfg = {};
    cfg.gridDim = grid;
    cfg.blockDim = block;
    cfg.dynamicSmemBytes = 0;
    cfg.stream = 0;                        // legacy default stream (captured)
    cudaLaunchAttribute at[1];
    at[0].id = cudaLaunchAttributeProgrammaticStreamSerialization;
    at[0].val.programmaticStreamSerializationAllowed = 1;
    cfg.attrs = at;
    cfg.numAttrs = 1;
    cudaLaunchKernelEx(&cfg, fn, args...);
}

// ---------------- launch ----------------
extern "C" void kernel_launch(void* const* d_in, const int* in_sizes, int n_in,
                              void* d_out, int out_size) {
    const float* wax   = (const float*)d_in[0];
    const float* blw   = (const float*)d_in[1];
    const float* blb   = (const float*)d_in[2];
    const float* w_ih0 = (const float*)d_in[3];
    // d_in[4] = w_hh0 (unused: h0 = 0)
    const float* b_ih0 = (const float*)d_in[5];
    const float* b_hh0 = (const float*)d_in[6];
    const float* w_ih1 = (const float*)d_in[7];
    const float* b_ih1 = (const float*)d_in[9];
    const float* b_hh1 = (const float*)d_in[10];
    const float* w_ih2 = (const float*)d_in[11];
    const float* b_ih2 = (const float*)d_in[13];
    const float* b_hh2 = (const float*)d_in[14];
    const float* lin_w = (const float*)d_in[15];
    const float* lin_b = (const float*)d_in[16];
    float* out = (float*)d_out;

    static float *p_v = nullptr, *p_ha = nullptr, *p_hb = nullptr, *p_o = nullptr;
    if (!p_v) {
        cudaGetSymbolAddress((void**)&p_v,  g_v);
        cudaGetSymbolAddress((void**)&p_ha, g_ha);
        cudaGetSymbolAddress((void**)&p_hb, g_hb);
        cudaGetSymbolAddress((void**)&p_o,  g_o);
    }

    const unsigned GLINES = (unsigned)((size_t)HH*HH*4/128);   // 131072 lines per gate region

    k_front<<<SYM, 128>>>(wax, blw, blb);

    // cell 0: proven config; prologue prefetch = 1 iteration (small window behind k_front).
    pdl_launch(dim3(HH), dim3(192),
               &k_cell<192, 8, HIN, 1, true, false, 1>,
               w_ih0, (const float*)p_v, b_ih0, b_hh0, (float*)p_ha,
               (const float*)nullptr, 0u, (const float*)nullptr, 0u);

    // cell 1: FULL own-stream prologue prefetch (lands in cell0's drain window)
    //         + in-loop 2-pass prefetch of w_ih2 (i and g regions).
    pdl_launch(dim3(HH/2), dim3(128),
               &k_cell<128, 8, HH, 2, true, true, 4>,
               w_ih1, (const float*)p_ha, b_ih1, b_hh1, (float*)p_hb,
               (const float*)(w_ih2 + (size_t)0*HH*HH), GLINES,
               (const float*)(w_ih2 + (size_t)2*HH*HH), GLINES);

    // cell 2: FULL own-stream prologue prefetch + in-loop prefetch of lin_w.
    pdl_launch(dim3(HH/2), dim3(128),
               &k_cell<128, 8, HH, 2, true, true, 4>,
               w_ih2, (const float*)p_hb, b_ih2, b_hh2, (float*)p_ha,
               (const float*)lin_w, (unsigned)((size_t)NO*HH*4/128),
               (const float*)nullptr, 0u);

    // linear head: full prologue prefetch (L2-hot already; belt and braces).
    pdl_launch(dim3(NO/4), dim3(128),
               &k_linw<HH, 4, 8>,
               lin_w, (const float*)p_ha, lin_b, (float*)p_o);

    // finalize. PDL off lin.
    pdl_launch(dim3(NS), dim3(512), &k_final, out);
}

// round 17
// speedup vs baseline: 1.1469x; 1.0498x over previous
#include <cuda_runtime.h>
#include <math.h>

#define NS 3
#define SYM 512
#define FD 20
#define NLIN 11
#define NOUT 9
#define HH 2048
#define HIN (NS*SYM*NOUT)   /* 13824 */
#define NO (NS*SYM)         /* 1536 */
#define EPSF 1e-9f

// ---------------- device scratch (no allocations allowed) ----------------
__device__ float g_v[HIN];
__device__ float g_ha[HH];
__device__ float g_hb[HH];
__device__ float g_o[NO];

// DFT twiddles: cos/sin(pi*m/10), m = 0..19 (exact fp32 literals)
__constant__ float c_cs[20] = {
     1.0f,            0.9510565163f,  0.8090169944f,  0.5877852523f,  0.3090169944f,
     0.0f,           -0.3090169944f, -0.5877852523f, -0.8090169944f, -0.9510565163f,
    -1.0f,           -0.9510565163f, -0.8090169944f, -0.5877852523f, -0.3090169944f,
     0.0f,            0.3090169944f,  0.5877852523f,  0.8090169944f,  0.9510565163f
};
__constant__ float c_sn[20] = {
     0.0f,            0.3090169944f,  0.5877852523f,  0.8090169944f,  0.9510565163f,
     1.0f,            0.9510565163f,  0.8090169944f,  0.5877852523f,  0.3090169944f,
     0.0f,           -0.3090169944f, -0.5877852523f, -0.8090169944f, -0.9510565163f,
    -1.0f,           -0.9510565163f, -0.8090169944f, -0.5877852523f, -0.3090169944f
};

// ---------------- front end: inorm -> DFT (table twiddles) -> bilinear -> leaky -> softmax(NS) ----------------
__global__ __launch_bounds__(128) void k_front(const float* __restrict__ wax,
                                               const float* __restrict__ blw,
                                               const float* __restrict__ blb) {
    int s = blockIdx.x;           // 0..511
    int tid = threadIdx.x;
    int warp = tid >> 5, lane = tid & 31;

    __shared__ float sh_xn[NS][FD];
    __shared__ float sh_re[NS][NLIN], sh_im[NS][NLIN];
    __shared__ float sh_z[NS][NOUT];

    if (warp < NS) {
        int b = warp;
        float x = 0.f;
        if (lane < FD) x = wax[(b*SYM + s)*FD + lane];
        float sum = x, sq = x*x;
        #pragma unroll
        for (int o = 16; o > 0; o >>= 1) {
            sum += __shfl_xor_sync(0xffffffffu, sum, o);
            sq  += __shfl_xor_sync(0xffffffffu, sq,  o);
        }
        float m = sum * (1.0f/FD);
        float var = sq * (1.0f/FD) - m*m;
        float r = rsqrtf(var + EPSF);
        if (lane < FD) sh_xn[b][lane] = (x - m) * r;
        __syncwarp();

        if (lane < NLIN) {
            float re = 0.f, im = 0.f;
            int idx = 0;                       // (lane*f) mod 20, tracked incrementally
            #pragma unroll
            for (int f = 0; f < FD; f++) {
                float xv = sh_xn[b][f];
                re += xv * c_cs[idx];
                im -= xv * c_sn[idx];
                idx += lane;
                if (idx >= FD) idx -= FD;
            }
            sh_re[b][lane] = re;
            sh_im[b][lane] = im;
        }
        __syncwarp();

        if (lane < NOUT) {
            int k = lane;
            float z = blb[k];
            #pragma unroll
            for (int i = 0; i < NLIN; i++) {
                float t = 0.f;
                #pragma unroll
                for (int j = 0; j < NLIN; j++)
                    t += blw[(k*NLIN + i)*NLIN + j] * sh_im[b][j];
                z += sh_re[b][i] * t;
            }
            z = (z >= 0.f) ? z : 0.01f*z;   // leaky_relu
            sh_z[b][k] = z;
        }
    }
    __syncthreads();

    if (tid < NOUT) {
        int k = tid;
        float z0 = sh_z[0][k], z1 = sh_z[1][k], z2 = sh_z[2][k];
        float m = fmaxf(z0, fmaxf(z1, z2));
        float e0 = expf(z0-m), e1 = expf(z1-m), e2 = expf(z2-m);
        float inv = 1.f/(e0+e1+e2);
        g_v[s*(NS*NOUT) + 0*NOUT + k] = e0*inv;
        g_v[s*(NS*NOUT) + 1*NOUT + k] = e1*inv;
        g_v[s*(NS*NOUT) + 2*NOUT + k] = e2*inv;
    }
}

__device__ __forceinline__ void pf_l2(const float* p) {
    asm volatile("prefetch.global.L2 [%0];" :: "l"(p));
}

// ---------------- fused LSTM cell (zero state): block computes i,g,o rows of JPB j's ----------------
// PDL: weight pointer setup + self-prefetch run BEFORE cudaGridDependencySynchronize()
// (predecessor-independent), landing in the predecessor's drain-wave DRAM headroom.
// PROITER: iterations of own weight lines prefetched pre-sync (H->H cells: ALL; cell0: 2).
// No in-loop prefetch: prologue prefetch by idle-waiting successor blocks is free,
// in-loop prefetch costs the host kernel ~0.9us/pass (R11/R14 measured).
template<int NT, int MINB, int N, int JPB, bool STREAM, int PROITER>
__global__ __launch_bounds__(NT, MINB) void k_cell(const float* __restrict__ W,
                                                   const float* __restrict__ x,
                                                   const float* __restrict__ b_ih,
                                                   const float* __restrict__ b_hh,
                                                   float* __restrict__ h) {
    constexpr int N4   = N / 4;
    constexpr int ITER = N4 / NT;       // exact by construction
    constexpr int NR   = 3 * JPB;
    const int j0 = blockIdx.x * JPB;
    const int tid = threadIdx.x;

    const float4* __restrict__ xv = (const float4*)x;
    const float4* Wr[NR];
    #pragma unroll
    for (int q = 0; q < JPB; q++) {
        int j = j0 + q;
        Wr[3*q + 0] = (const float4*)(W + (size_t)(0*HH + j) * N);  // i
        Wr[3*q + 1] = (const float4*)(W + (size_t)(2*HH + j) * N);  // g
        Wr[3*q + 2] = (const float4*)(W + (size_t)(3*HH + j) * N);  // o
    }

    // predecessor-independent prologue: warm own weight lines into L2
    #pragma unroll
    for (int it = 0; it < PROITER; it++) {
        #pragma unroll
        for (int r = 0; r < NR; r++) pf_l2((const float*)(Wr[r] + tid + it*NT));
    }

    cudaGridDependencySynchronize();    // wait for predecessor's writes (x)

    float acc[NR];
    #pragma unroll
    for (int r = 0; r < NR; r++) acc[r] = 0.f;

    #pragma unroll 6
    for (int it = 0; it < ITER; it++) {
        int t = tid + it * NT;
        float4 v = xv[t];
        #pragma unroll
        for (int r = 0; r < NR; r++) {
            float4 w = STREAM ? __ldcs(&Wr[r][t]) : Wr[r][t];
            acc[r] += w.x*v.x + w.y*v.y + w.z*v.z + w.w*v.w;
        }
    }

    __shared__ float sred[NR][NT/32];
    #pragma unroll
    for (int r = 0; r < NR; r++) {
        float a = acc[r];
        #pragma unroll
        for (int o = 16; o > 0; o >>= 1) a += __shfl_xor_sync(0xffffffffu, a, o);
        if ((tid & 31) == 0) sred[r][tid >> 5] = a;
    }
    __syncthreads();

    if (tid < JPB) {
        int q = tid, j = j0 + q;
        float gi = 0.f, gg = 0.f, go = 0.f;
        #pragma unroll
        for (int w = 0; w < NT/32; w++) {
            gi += sred[3*q + 0][w];
            gg += sred[3*q + 1][w];
            go += sred[3*q + 2][w];
        }
        gi += b_ih[j]        + b_hh[j];
        gg += b_ih[2*HH + j] + b_hh[2*HH + j];
        go += b_ih[3*HH + j] + b_hh[3*HH + j];
        float si = 1.f / (1.f + __expf(-gi));
        float so = 1.f / (1.f + __expf(-go));
        float c  = si * tanhf(gg);
        h[j] = so * tanhf(c);
    }
}

// ---------------- warp-per-row linear head (PDL; full own-stream prologue prefetch) ----------------
template<int N, int WPB, int UNR>
__global__ __launch_bounds__(WPB*32) void k_linw(const float* __restrict__ W,
                                                 const float* __restrict__ x,
                                                 const float* __restrict__ b,
                                                 float* __restrict__ out) {
    constexpr int R = N / 128;
    const int warp = threadIdx.x >> 5, lane = threadIdx.x & 31;
    const int row = blockIdx.x * WPB + warp;

    const float4* __restrict__ xv = (const float4*)x;
    const float4* __restrict__ wr = (const float4*)(W + (size_t)row * N);

    #pragma unroll
    for (int k = 0; k < R; k++) pf_l2((const float*)(wr + lane + 32*k));  // pre-sync warm
    cudaGridDependencySynchronize();

    float acc = 0.f;
    #pragma unroll UNR
    for (int k = 0; k < R; k++) {
        int t = lane + 32*k;
        float4 v = xv[t];
        float4 w = wr[t];
        acc += w.x*v.x + w.y*v.y + w.z*v.z + w.w*v.w;
    }
    #pragma unroll
    for (int o = 16; o > 0; o >>= 1) acc += __shfl_xor_sync(0xffffffffu, acc, o);
    if (lane == 0) out[row] = acc + b[row];
}

// ---------------- final: inorm(512) -> leaky -> softmax(512), 3 blocks (PDL) ----------------
__device__ __forceinline__ float blk_sum512(float v, volatile float* sh) {
    int t = threadIdx.x;
    #pragma unroll
    for (int o = 16; o > 0; o >>= 1) v += __shfl_xor_sync(0xffffffffu, v, o);
    if ((t & 31) == 0) sh[t >> 5] = v;
    __syncthreads();
    if (t == 0) {
        float a = 0.f;
        #pragma unroll
        for (int w = 0; w < 16; w++) a += sh[w];
        sh[16] = a;
    }
    __syncthreads();
    float r = sh[16];
    __syncthreads();
    return r;
}

__device__ __forceinline__ float blk_max512(float v, volatile float* sh) {
    int t = threadIdx.x;
    #pragma unroll
    for (int o = 16; o > 0; o >>= 1) v = fmaxf(v, __shfl_xor_sync(0xffffffffu, v, o));
    if ((t & 31) == 0) sh[t >> 5] = v;
    __syncthreads();
    if (t == 0) {
        float a = -3.4e38f;
        #pragma unroll
        for (int w = 0; w < 16; w++) a = fmaxf(a, sh[w]);
        sh[16] = a;
    }
    __syncthreads();
    float r = sh[16];
    __syncthreads();
    return r;
}

__global__ __launch_bounds__(512) void k_final(float* __restrict__ out) {
    __shared__ float sh[17];
    cudaGridDependencySynchronize();
    int b = blockIdx.x;   // 0..2
    int t = threadIdx.x;  // 0..511
    float v = g_o[b*SYM + t];
    float sum = blk_sum512(v, sh);
    float sq  = blk_sum512(v*v, sh);
    float m = sum * (1.0f/SYM);
    float var = sq * (1.0f/SYM) - m*m;
    float xn = (v - m) * rsqrtf(var + EPSF);
    xn = (xn >= 0.f) ? xn : 0.01f*xn;
    float mx = blk_max512(xn, sh);
    float e = expf(xn - mx);
    float se = blk_sum512(e, sh);
    out[b*SYM + t] = e / se;
}

// ---------------- PDL launch helper ----------------
template<typename F, typename... Args>
static void pdl_launch(dim3 grid, dim3 block, F* fn, Args... args) {
    cudaLaunchConfig_t cfg = {};
    cfg.gridDim = grid;
    cfg.blockDim = block;
    cfg.dynamicSmemBytes = 0;
    cfg.stream = 0;                        // legacy default stream (captured)
    cudaLaunchAttribute at[1];
    at[0].id = cudaLaunchAttributeProgrammaticStreamSerialization;
    at[0].val.programmaticStreamSerializationAllowed = 1;
    cfg.attrs = at;
    cfg.numAttrs = 1;
    cudaLaunchKernelEx(&cfg, fn, args...);
}

// ---------------- launch ----------------
extern "C" void kernel_launch(void* const* d_in, const int* in_sizes, int n_in,
                              void* d_out, int out_size) {
    const float* wax   = (const float*)d_in[0];
    const float* blw   = (const float*)d_in[1];
    const float* blb   = (const float*)d_in[2];
    const float* w_ih0 = (const float*)d_in[3];
    // d_in[4] = w_hh0 (unused: h0 = 0)
    const float* b_ih0 = (const float*)d_in[5];
    const float* b_hh0 = (const float*)d_in[6];
    const float* w_ih1 = (const float*)d_in[7];
    const float* b_ih1 = (const float*)d_in[9];
    const float* b_hh1 = (const float*)d_in[10];
    const float* w_ih2 = (const float*)d_in[11];
    const float* b_ih2 = (const float*)d_in[13];
    const float* b_hh2 = (const float*)d_in[14];
    const float* lin_w = (const float*)d_in[15];
    const float* lin_b = (const float*)d_in[16];
    float* out = (float*)d_out;

    static float *p_v = nullptr, *p_ha = nullptr, *p_hb = nullptr, *p_o = nullptr;
    if (!p_v) {
        cudaGetSymbolAddress((void**)&p_v,  g_v);
        cudaGetSymbolAddress((void**)&p_ha, g_ha);
        cudaGetSymbolAddress((void**)&p_hb, g_hb);
        cudaGetSymbolAddress((void**)&p_o,  g_o);
    }

    k_front<<<SYM, 128>>>(wax, blw, blb);

    // cell 0: proven config; prologue prefetch = 2 iterations (free, small window behind k_front).
    pdl_launch(dim3(HH), dim3(192),
               &k_cell<192, 8, HIN, 1, true, 2>,
               w_ih0, (const float*)p_v, b_ih0, b_hh0, (float*)p_ha);

    // cell 1: clean stream (no in-loop PF); FULL own-stream prologue prefetch
    //         lands in cell0's drain window.
    pdl_launch(dim3(HH/2), dim3(128),
               &k_cell<128, 8, HH, 2, true, 4>,
               w_ih1, (const float*)p_ha, b_ih1, b_hh1, (float*)p_hb);

    // cell 2: clean stream; FULL own-stream prologue prefetch in cell1's drain window.
    pdl_launch(dim3(HH/2), dim3(128),
               &k_cell<128, 8, HH, 2, true, 4>,
               w_ih2, (const float*)p_hb, b_ih2, b_hh2, (float*)p_ha);

    // linear head: full prologue prefetch in cell2's drain window.
    pdl_launch(dim3(NO/4), dim3(128),
               &k_linw<HH, 4, 8>,
               lin_w, (const float*)p_ha, lin_b, (float*)p_o);

    // finalize. PDL off lin.
    pdl_launch(dim3(NS), dim3(512), &k_final, out);
}